// round 2
// baseline (speedup 1.0000x reference)
#include <cuda_runtime.h>
#include <cuda_bf16.h>
#include <cstdint>

// ---------------------------------------------------------------------------
// Problem constants
// ---------------------------------------------------------------------------
#define BB     8
#define NN     256
#define FD     1024
#define HH     256
#define M_ROWS (BB * NN)          // 2048
#define NOUT   (2 * HH)           // 512  (pr || pc)
#define KSEL   39321              // int(0.6 * 256 * 256)
#define QSZ    (BB * NN * NN)     // 524288 per output tensor

// Scratch (device globals — no allocation allowed)
__device__ float g_pr[M_ROWS * HH];   // pr + b1
__device__ float g_pc[M_ROWS * HH];
__device__ float g_max[BB];
__device__ float g_sum[BB];
__device__ float g_thr[BB];
__device__ float g_tsum[BB];

// ---------------------------------------------------------------------------
// Packed fp32x2 FMA (Blackwell FFMA2)
// ---------------------------------------------------------------------------
__device__ __forceinline__ void fma2(unsigned long long& d,
                                     unsigned long long a,
                                     unsigned long long b) {
    asm("fma.rn.f32x2 %0, %1, %2, %0;" : "+l"(d) : "l"(a), "l"(b));
}

// ---------------------------------------------------------------------------
// Kernel 1: fused GEMM  y[m, n] = sum_k x[m,k] * Wcat[n,k]
//   n <  256 : Wcat row = W1[n, 0:1024]      -> g_pr (+ b1[n])
//   n >= 256 : Wcat row = W1[n-256, 1024:]   -> g_pc
// BM=64, BN=128, 128 threads, 8x8 (k-packed float2) per thread.
// ---------------------------------------------------------------------------
__global__ __launch_bounds__(128) void gemm_kernel(const float* __restrict__ x,
                                                   const float* __restrict__ W1,
                                                   const float* __restrict__ b1) {
    __shared__ unsigned long long As[8][66];    // [kp][m]   (pad: 66)
    __shared__ unsigned long long Bs[8][130];   // [kp][perm(n)] (pad: 130)

    const unsigned long long* xg = (const unsigned long long*)x;   // 512 ull / row
    const unsigned long long* wg = (const unsigned long long*)W1;  // 1024 ull / row

    const int tid = threadIdx.x;
    const int tx  = tid & 15;     // n dim (16 * 8 = 128)
    const int ty  = tid >> 4;     // m dim (8  * 8 = 64)
    const int bm  = blockIdx.y * 64;
    const int bn  = blockIdx.x * 128;

    // loader mapping: idx = tid + u*128 ; row = idx>>3 ; kp = idx&7
    const int lrow = tid >> 3;    // 0..15
    const int lkp  = tid & 7;

    // A: 4 ull per thread (rows lrow+16u), B: 8 ull (cols lrow+16u)
    const int sel  = (bn >= 256) ? 1 : 0;
    const long abase = (long)(bm + lrow) * 512 + lkp;
    const long bbase = (long)(bn - sel * 256 + lrow) * 1024 + sel * 512 + lkp;

    int bsidx[8];
#pragma unroll
    for (int u = 0; u < 8; u++) {
        int nl = lrow + 16 * u;          // 0..127
        int q = nl >> 1, lane = nl & 1;  // chunk permutation for conflict-free reads
        bsidx[u] = ((q & 3) * 16 + (q >> 2)) * 2 + lane;
    }

    unsigned long long acc[8][8];
#pragma unroll
    for (int r = 0; r < 8; r++)
#pragma unroll
        for (int c = 0; c < 8; c++) acc[r][c] = 0ull;

    const unsigned long long* ap = xg + abase;
    const unsigned long long* bp = wg + bbase;

    unsigned long long ra[4], rb[8];
#pragma unroll
    for (int u = 0; u < 4; u++) ra[u] = ap[(long)u * 8192];
#pragma unroll
    for (int u = 0; u < 8; u++) rb[u] = bp[(long)u * 16384];

    for (int it = 0; it < 64; it++) {
#pragma unroll
        for (int u = 0; u < 4; u++) As[lkp][lrow + 16 * u] = ra[u];
#pragma unroll
        for (int u = 0; u < 8; u++) Bs[lkp][bsidx[u]] = rb[u];
        __syncthreads();

        if (it < 63) {
            ap += 8; bp += 8;
#pragma unroll
            for (int u = 0; u < 4; u++) ra[u] = ap[(long)u * 8192];
#pragma unroll
            for (int u = 0; u < 8; u++) rb[u] = bp[(long)u * 16384];
        }

#pragma unroll
        for (int kp = 0; kp < 8; kp++) {
            unsigned long long a[8], bv[8];
#pragma unroll
            for (int c = 0; c < 4; c++) {
                ulonglong2 t = *(const ulonglong2*)&As[kp][ty * 8 + c * 2];
                a[c * 2] = t.x; a[c * 2 + 1] = t.y;
                ulonglong2 s2 = *(const ulonglong2*)&Bs[kp][(c * 16 + tx) * 2];
                bv[c * 2] = s2.x; bv[c * 2 + 1] = s2.y;
            }
#pragma unroll
            for (int r = 0; r < 8; r++)
#pragma unroll
                for (int c = 0; c < 8; c++)
                    fma2(acc[r][c], a[r], bv[c]);
        }
        __syncthreads();
    }

    // epilogue
#pragma unroll
    for (int r = 0; r < 8; r++) {
        int m = bm + ty * 8 + r;
#pragma unroll
        for (int c = 0; c < 8; c++) {
            int n = bn + tx * 8 + c;
            float2 f = *reinterpret_cast<float2*>(&acc[r][c]);
            float v = f.x + f.y;
            if (n < 256) g_pr[m * 256 + n] = v + b1[n];
            else         g_pc[m * 256 + (n - 256)] = v;
        }
    }
}

// ---------------------------------------------------------------------------
// Kernel 2: edge[b,i,j] = sum_h relu(pr[b,i,h] + pc[b,j,h]) * W2[h] + b2
// 64x64 tile per block, 256 threads, 4x4 per thread, h-major smem staging.
// ---------------------------------------------------------------------------
__global__ __launch_bounds__(256) void edge_kernel(const float* __restrict__ W2,
                                                   const float* __restrict__ b2,
                                                   float* __restrict__ out_edge) {
    extern __shared__ float smem_e[];
    float* spr = smem_e;              // [256][64]  (h-major)
    float* spc = smem_e + 16384;      // [256][64]
    float* sw2 = smem_e + 32768;      // [256]

    const int tid = threadIdx.x;
    const int b  = blockIdx.z;
    const int i0 = blockIdx.y * 64;
    const int j0 = blockIdx.x * 64;

    sw2[tid] = W2[tid];

    const float4* pr4 = (const float4*)g_pr;
    const float4* pc4 = (const float4*)g_pc;
#pragma unroll
    for (int u = 0; u < 16; u++) {
        int t = tid + u * 256;      // 0..4095
        int i  = t & 63;
        int hq = t >> 6;            // 0..63 (float4 over h)
        float4 v = pr4[(b * 256 + i0 + i) * 64 + hq];
        spr[(hq * 4 + 0) * 64 + i] = v.x;
        spr[(hq * 4 + 1) * 64 + i] = v.y;
        spr[(hq * 4 + 2) * 64 + i] = v.z;
        spr[(hq * 4 + 3) * 64 + i] = v.w;
        float4 w = pc4[(b * 256 + j0 + i) * 64 + hq];
        spc[(hq * 4 + 0) * 64 + i] = w.x;
        spc[(hq * 4 + 1) * 64 + i] = w.y;
        spc[(hq * 4 + 2) * 64 + i] = w.z;
        spc[(hq * 4 + 3) * 64 + i] = w.w;
    }
    __syncthreads();

    const int tx = tid & 15;   // j
    const int ty = tid >> 4;   // i
    float acc[4][4];
#pragma unroll
    for (int r = 0; r < 4; r++)
#pragma unroll
        for (int c = 0; c < 4; c++) acc[r][c] = 0.f;

#pragma unroll 4
    for (int h = 0; h < 256; h++) {
        float4 a = *(const float4*)&spr[h * 64 + ty * 4];
        float4 cjs = *(const float4*)&spc[h * 64 + tx * 4];
        float w = sw2[h];
        float av[4] = {a.x, a.y, a.z, a.w};
        float cv[4] = {cjs.x, cjs.y, cjs.z, cjs.w};
#pragma unroll
        for (int r = 0; r < 4; r++)
#pragma unroll
            for (int c = 0; c < 4; c++) {
                float t = av[r] + cv[c];
                t = fmaxf(t, 0.f);
                acc[r][c] = fmaf(t, w, acc[r][c]);
            }
    }

    const float bbv = b2[0];
#pragma unroll
    for (int r = 0; r < 4; r++) {
        int i = i0 + ty * 4 + r;
        float4 o;
        o.x = acc[r][0] + bbv;
        o.y = acc[r][1] + bbv;
        o.z = acc[r][2] + bbv;
        o.w = acc[r][3] + bbv;
        *(float4*)&out_edge[b * 65536 + i * 256 + j0 + tx * 4] = o;
    }
}

// ---------------------------------------------------------------------------
// Kernel 3: per-batch max and sum(exp(2*(s - max)))
// ---------------------------------------------------------------------------
__global__ void reduce_kernel(const float* __restrict__ edge) {
    __shared__ float red[256];
    const int b = blockIdx.x, tid = threadIdx.x;
    const float* s = edge + b * 65536;

    float m = -3.4e38f;
#pragma unroll 8
    for (int i = tid; i < 65536; i += 256) m = fmaxf(m, s[i]);
    red[tid] = m; __syncthreads();
    for (int o = 128; o > 0; o >>= 1) {
        if (tid < o) red[tid] = fmaxf(red[tid], red[tid + o]);
        __syncthreads();
    }
    const float M = red[0];
    __syncthreads();

    float sum = 0.f;
#pragma unroll 8
    for (int i = tid; i < 65536; i += 256) sum += expf(2.f * (s[i] - M));
    red[tid] = sum; __syncthreads();
    for (int o = 128; o > 0; o >>= 1) {
        if (tid < o) red[tid] += red[tid + o];
        __syncthreads();
    }
    if (tid == 0) { g_max[b] = M; g_sum[b] = red[0]; }
}

// ---------------------------------------------------------------------------
// Kernel 4: soft_mask = exp(2*(s - max)) / sum
// ---------------------------------------------------------------------------
__global__ void softmax_kernel(const float* __restrict__ edge,
                               float* __restrict__ soft) {
    int idx = blockIdx.x * 256 + threadIdx.x;
    int b = idx >> 16;
    soft[idx] = expf(2.f * (edge[idx] - g_max[b])) / g_sum[b];
}

// ---------------------------------------------------------------------------
// Kernel 5: exact k-th largest (radix select on positive-float bits) + topsum
// ---------------------------------------------------------------------------
__global__ void select_kernel(const float* __restrict__ soft) {
    __shared__ unsigned int hist[256];
    __shared__ unsigned int s_prefix;
    __shared__ int s_r;
    __shared__ float red[256];

    const int b = blockIdx.x, tid = threadIdx.x;
    const unsigned int* v = (const unsigned int*)(soft + b * 65536);

    if (tid == 0) { s_prefix = 0u; s_r = KSEL; }
    __syncthreads();

    for (int pass = 0; pass < 4; pass++) {
        const int shift = 24 - pass * 8;
        hist[tid] = 0u;
        __syncthreads();
        const unsigned int pref = s_prefix;
        for (int i = tid; i < 65536; i += 256) {
            unsigned int u = v[i];
            bool ok = (pass == 0) || ((u >> (shift + 8)) == pref);
            if (ok) atomicAdd(&hist[(u >> shift) & 255u], 1u);
        }
        __syncthreads();
        if (tid == 0) {
            unsigned int cum = 0; int r = s_r; int bin = 0;
            for (int bb = 255; bb >= 0; bb--) {
                unsigned int c = hist[bb];
                if ((int)(cum + c) >= r) { bin = bb; break; }
                cum += c;
            }
            s_prefix = (s_prefix << 8) | (unsigned int)bin;
            s_r = r - (int)cum;
        }
        __syncthreads();
    }

    const float thr = __uint_as_float(s_prefix);
    const float* f = soft + b * 65536;
    float sum = 0.f;
#pragma unroll 8
    for (int i = tid; i < 65536; i += 256) {
        float x = f[i];
        if (x >= thr) sum += x;
    }
    red[tid] = sum; __syncthreads();
    for (int o = 128; o > 0; o >>= 1) {
        if (tid < o) red[tid] += red[tid + o];
        __syncthreads();
    }
    if (tid == 0) { g_thr[b] = thr; g_tsum[b] = red[0]; }
}

// ---------------------------------------------------------------------------
// Kernel 6: causal / conf masks
// ---------------------------------------------------------------------------
__global__ void finalize_kernel(const float* __restrict__ soft,
                                float* __restrict__ causal,
                                float* __restrict__ conf) {
    int idx = blockIdx.x * 256 + threadIdx.x;
    int b = idx >> 16;
    float v = soft[idx];
    float c = (v >= g_thr[b]) ? v / (g_tsum[b] + 1e-12f) : 0.f;
    causal[idx] = c;
    conf[idx] = 1.f - c;
}

// ---------------------------------------------------------------------------
// Launch
// ---------------------------------------------------------------------------
extern "C" void kernel_launch(void* const* d_in, const int* in_sizes, int n_in,
                              void* d_out, int out_size) {
    const float* x  = (const float*)d_in[0];
    const float* W1 = (const float*)d_in[1];
    const float* b1 = (const float*)d_in[2];
    const float* W2 = (const float*)d_in[3];
    const float* b2 = (const float*)d_in[4];

    float* out = (float*)d_out;
    float* o_causal = out;
    float* o_conf   = out + QSZ;
    float* o_edge   = out + 2 * QSZ;
    float* o_soft   = out + 3 * QSZ;

    const int edge_smem = 33024 * 4;   // 132096 bytes
    cudaFuncSetAttribute(edge_kernel, cudaFuncAttributeMaxDynamicSharedMemorySize,
                         edge_smem);

    gemm_kernel<<<dim3(4, 32), 128>>>(x, W1, b1);
    edge_kernel<<<dim3(4, 4, BB), 256, edge_smem>>>(W2, b2, o_edge);
    reduce_kernel<<<BB, 256>>>(o_edge);
    softmax_kernel<<<QSZ / 256, 256>>>(o_edge, o_soft);
    select_kernel<<<BB, 256>>>(o_soft);
    finalize_kernel<<<QSZ / 256, 256>>>(o_soft, o_causal, o_conf);
}